// round 3
// baseline (speedup 1.0000x reference)
#include <cuda_runtime.h>
#include <cstdint>

// ---------------- problem constants ----------------
#define NN 100000
#define NE 3200000
#define GG 64

// ---------------- f32x2 packed FMA helpers (sm_100+ only, via PTX) --------
#define FMA_F32X2(d, a, b) \
    asm("fma.rn.f32x2 %0, %1, %2, %0;" : "+l"(d) : "l"(a), "l"(b))

__device__ __forceinline__ uint64_t dup_f32(float x) {
    uint64_t d;
    uint32_t u = __float_as_uint(x);
    asm("mov.b64 %0, {%1, %1};" : "=l"(d) : "r"(u));
    return d;
}

__device__ __forceinline__ void unpack_f32x2(uint64_t v, float& lo, float& hi) {
    uint32_t a, b;
    asm("mov.b64 {%0, %1}, %2;" : "=r"(a), "=r"(b) : "l"(v));
    lo = __uint_as_float(a);
    hi = __uint_as_float(b);
}

// ---------------- device scratch (no allocs allowed) ----------------
__device__ float g_y[NN * 64];          // dis-scaled x@W
__device__ float g_local[NN * 256];     // concat of 4 layer outputs
__device__ float g_h1[NN * 256];        // enc layer-1 output
__device__ float g_h2[NN * 128];        // enc layer-2 output
__device__ float g_dis[NN];
__device__ int   g_cnt[NN];
__device__ int   g_excl[NN];
__device__ int   g_rowptr[NN + 1];
__device__ int   g_woff[NN];
__device__ int   g_src[NE];
__device__ int   g_bsums[128];
__device__ float g_gsum[GG * 128];
__device__ float g_gcnt[GG];

// ---------------- degree / dis ----------------
__global__ void k_init_cnt(int n) {
    int i = blockIdx.x * blockDim.x + threadIdx.x;
    if (i < n) g_cnt[i] = 1;  // self loop
}

__global__ void k_deg(const int* __restrict__ ei, int ne) {
    int i = blockIdx.x * blockDim.x + threadIdx.x;
    if (i < ne) atomicAdd(&g_cnt[ei[ne + i]], 1);  // col = target
}

__global__ void k_dis(int n) {
    int i = blockIdx.x * blockDim.x + threadIdx.x;
    if (i < n) g_dis[i] = rsqrtf((float)g_cnt[i]);
}

// ---------------- prefix scan for CSR (counts = cnt-1 = in-degree) --------
__global__ void k_scanA(int n) {
    __shared__ int sh[1024];
    int tid = threadIdx.x;
    int i = blockIdx.x * 1024 + tid;
    int v = (i < n) ? (g_cnt[i] - 1) : 0;
    sh[tid] = v;
    __syncthreads();
    for (int off = 1; off < 1024; off <<= 1) {
        int t = (tid >= off) ? sh[tid - off] : 0;
        __syncthreads();
        sh[tid] += t;
        __syncthreads();
    }
    if (i < n) g_excl[i] = sh[tid] - v;  // exclusive within block
    if (tid == 1023) g_bsums[blockIdx.x] = sh[1023];
}

__global__ void k_scanB(int nb) {
    if (threadIdx.x == 0 && blockIdx.x == 0) {
        int run = 0;
        for (int b = 0; b < nb; b++) {
            int t = g_bsums[b];
            g_bsums[b] = run;
            run += t;
        }
    }
}

__global__ void k_scanC(int n, int ne) {
    int i = blockIdx.x * blockDim.x + threadIdx.x;
    if (i < n) {
        int rp = g_excl[i] + g_bsums[i >> 10];
        g_rowptr[i] = rp;
        g_woff[i] = rp;
    }
    if (i == 0) g_rowptr[n] = ne;
}

__global__ void k_scatter(const int* __restrict__ ei, int ne) {
    int i = blockIdx.x * blockDim.x + threadIdx.x;
    if (i < ne) {
        int c = ei[ne + i];
        int pos = atomicAdd(&g_woff[c], 1);
        g_src[pos] = ei[i];  // row = source
    }
}

// ---------------- conv GEMM: y = (Xin @ W_l) * dis[row] ----------------
// block: 64x64 tile, 256 threads, 4x4/thread, M-paired f32x2 + dup-B smem
__global__ __launch_bounds__(256) void k_conv_gemm(
    const float* __restrict__ X0, const float* __restrict__ W,
    int n, int layer) {
    __shared__ float As[64][68];               // k-major: As[k][row]
    __shared__ unsigned long long Wsd[64][64]; // dup pairs (b,b)
    int tid = threadIdx.x;
    int rowBase = blockIdx.x * 64;

    for (int idx = tid; idx < 4096; idx += 256) {
        int k = idx >> 6, c = idx & 63;
        Wsd[k][c] = dup_f32(W[idx]);
    }
    for (int idx = tid; idx < 4096; idx += 256) {
        int r = idx >> 6, k = idx & 63;
        int gr = rowBase + r;
        float v = 0.f;
        if (gr < n) {
            if (layer == 0) v = X0[gr * 64 + k];
            else            v = g_local[gr * 256 + (layer - 1) * 64 + k];
        }
        As[k][r] = v;
    }
    __syncthreads();

    int tx = tid & 15, ty = tid >> 4;
    int c4 = tx * 4, r0 = ty * 4;
    uint64_t acc2[2][4] = {};  // [M-pair][col]
#pragma unroll
    for (int k = 0; k < 64; k++) {
        ulonglong2 ap = *(const ulonglong2*)&As[k][r0];    // rows r0..r0+3
        ulonglong2 b0 = *(const ulonglong2*)&Wsd[k][c4];   // cols c4,c4+1
        ulonglong2 b1 = *(const ulonglong2*)&Wsd[k][c4 + 2];
        FMA_F32X2(acc2[0][0], ap.x, b0.x);
        FMA_F32X2(acc2[0][1], ap.x, b0.y);
        FMA_F32X2(acc2[0][2], ap.x, b1.x);
        FMA_F32X2(acc2[0][3], ap.x, b1.y);
        FMA_F32X2(acc2[1][0], ap.y, b0.x);
        FMA_F32X2(acc2[1][1], ap.y, b0.y);
        FMA_F32X2(acc2[1][2], ap.y, b1.x);
        FMA_F32X2(acc2[1][3], ap.y, b1.y);
    }
#pragma unroll
    for (int p = 0; p < 2; p++) {
        float lo[4], hi[4];
#pragma unroll
        for (int c = 0; c < 4; c++) unpack_f32x2(acc2[p][c], lo[c], hi[c]);
        int gr0 = rowBase + r0 + 2 * p;
        int gr1 = gr0 + 1;
        if (gr0 < n) {
            float d = g_dis[gr0];
            float4 v = {lo[0] * d, lo[1] * d, lo[2] * d, lo[3] * d};
            *(float4*)&g_y[gr0 * 64 + c4] = v;
        }
        if (gr1 < n) {
            float d = g_dis[gr1];
            float4 v = {hi[0] * d, hi[1] * d, hi[2] * d, hi[3] * d};
            *(float4*)&g_y[gr1 * 64 + c4] = v;
        }
    }
}

// ---------------- aggregation + BN + relu + skip (warp per node) ----------
__global__ __launch_bounds__(256) void k_agg(
    int n, int layer,
    const float* __restrict__ bias, const float* __restrict__ gamma,
    const float* __restrict__ beta, const float* __restrict__ mean,
    const float* __restrict__ var) {
    int warp = (blockIdx.x * blockDim.x + threadIdx.x) >> 5;
    int lane = threadIdx.x & 31;
    if (warp >= n) return;
    int c = warp;
    int start = g_rowptr[c], end = g_rowptr[c + 1];
    const float2* y2 = (const float2*)g_y;
    float2 acc = y2[c * 32 + lane];  // self loop
    for (int e = start; e < end; e++) {
        int r = g_src[e];
        float2 v = y2[r * 32 + lane];
        acc.x += v.x;
        acc.y += v.y;
    }
    float dc = g_dis[c];
    int d0 = 2 * lane;

    float2 ga = *(const float2*)&gamma[d0];
    float2 va = *(const float2*)&var[d0];
    float2 bi = *(const float2*)&bias[d0];
    float2 me = *(const float2*)&mean[d0];
    float2 be = *(const float2*)&beta[d0];
    float s0 = ga.x * rsqrtf(va.x + 1e-5f);
    float s1 = ga.y * rsqrtf(va.y + 1e-5f);
    float v0 = (acc.x * dc + bi.x - me.x) * s0 + be.x;
    float v1 = (acc.y * dc + bi.y - me.y) * s1 + be.y;
    v0 = fmaxf(v0, 0.f);
    v1 = fmaxf(v1, 0.f);
    if (layer == 2) {  // skip: += previous_outputs[0] (cols 0..63)
        float2 pv = *(const float2*)&g_local[c * 256 + d0];
        v0 += pv.x;
        v1 += pv.y;
    }
    float2 outv = {v0, v1};
    *(float2*)&g_local[c * 256 + layer * 64 + d0] = outv;
}

// ---------------- encoder GEMMs: out = relu(A @ B + bias) ----------------
// BM=128, BN=128, BK=16; 256 threads; 8x8/thread, M-paired f32x2 + dup-B.
// mode 0: A=g_local (ld 256), out=g_h1 (ld 256)
// mode 1: A=g_h1    (ld 256), out=g_h2 (ld 128)
__global__ __launch_bounds__(256) void k_enc_gemm(
    const float* __restrict__ B, const float* __restrict__ bias,
    int K, int ncols, int mode, int n) {
    __shared__ float As[16][132];               // k-major
    __shared__ unsigned long long Bsd[16][128]; // dup pairs
    const float* A = (mode == 0) ? g_local : g_h1;
    float* O = (mode == 0) ? g_h1 : g_h2;
    const int lda = 256;
    const int ldo = (mode == 0) ? 256 : 128;
    int rowBase = blockIdx.x * 128;
    int colBase = blockIdx.y * 128;
    int tid = threadIdx.x;
    int tx = tid & 15, ty = tid >> 4;
    int r0 = ty * 8, cb0 = tx * 8;
    uint64_t acc2[4][8] = {};  // [M-pair][col]

    for (int kb = 0; kb < K; kb += 16) {
        for (int idx = tid; idx < 128 * 16; idx += 256) {
            int r = idx >> 4, k = idx & 15;
            int gr = rowBase + r;
            As[k][r] = (gr < n) ? A[gr * lda + kb + k] : 0.f;
        }
        for (int idx = tid; idx < 16 * 128; idx += 256) {
            int kk = idx >> 7, cc = idx & 127;
            Bsd[kk][cc] = dup_f32(B[(kb + kk) * ncols + colBase + cc]);
        }
        __syncthreads();
#pragma unroll
        for (int k = 0; k < 16; k++) {
            ulonglong2 ap01 = *(const ulonglong2*)&As[k][r0];      // pairs 0,1
            ulonglong2 ap23 = *(const ulonglong2*)&As[k][r0 + 4];  // pairs 2,3
            ulonglong2 bq0 = *(const ulonglong2*)&Bsd[k][cb0];
            ulonglong2 bq1 = *(const ulonglong2*)&Bsd[k][cb0 + 2];
            ulonglong2 bq2 = *(const ulonglong2*)&Bsd[k][cb0 + 4];
            ulonglong2 bq3 = *(const ulonglong2*)&Bsd[k][cb0 + 6];
            uint64_t ap[4] = {ap01.x, ap01.y, ap23.x, ap23.y};
            uint64_t bd[8] = {bq0.x, bq0.y, bq1.x, bq1.y,
                              bq2.x, bq2.y, bq3.x, bq3.y};
#pragma unroll
            for (int p = 0; p < 4; p++) {
#pragma unroll
                for (int cc = 0; cc < 8; cc++) {
                    FMA_F32X2(acc2[p][cc], ap[p], bd[cc]);
                }
            }
        }
        __syncthreads();
    }
    int cb = colBase + cb0;
    float4 bb0 = *(const float4*)&bias[cb];
    float4 bb1 = *(const float4*)&bias[cb + 4];
#pragma unroll
    for (int p = 0; p < 4; p++) {
        float lo[8], hi[8];
#pragma unroll
        for (int cc = 0; cc < 8; cc++) unpack_f32x2(acc2[p][cc], lo[cc], hi[cc]);
        int gr0 = rowBase + r0 + 2 * p;
        int gr1 = gr0 + 1;
        if (gr0 < n) {
            float4 v0 = {fmaxf(lo[0] + bb0.x, 0.f), fmaxf(lo[1] + bb0.y, 0.f),
                         fmaxf(lo[2] + bb0.z, 0.f), fmaxf(lo[3] + bb0.w, 0.f)};
            float4 v1 = {fmaxf(lo[4] + bb1.x, 0.f), fmaxf(lo[5] + bb1.y, 0.f),
                         fmaxf(lo[6] + bb1.z, 0.f), fmaxf(lo[7] + bb1.w, 0.f)};
            *(float4*)&O[gr0 * ldo + cb] = v0;
            *(float4*)&O[gr0 * ldo + cb + 4] = v1;
        }
        if (gr1 < n) {
            float4 v0 = {fmaxf(hi[0] + bb0.x, 0.f), fmaxf(hi[1] + bb0.y, 0.f),
                         fmaxf(hi[2] + bb0.z, 0.f), fmaxf(hi[3] + bb0.w, 0.f)};
            float4 v1 = {fmaxf(hi[4] + bb1.x, 0.f), fmaxf(hi[5] + bb1.y, 0.f),
                         fmaxf(hi[6] + bb1.z, 0.f), fmaxf(hi[7] + bb1.w, 0.f)};
            *(float4*)&O[gr1 * ldo + cb] = v0;
            *(float4*)&O[gr1 * ldo + cb + 4] = v1;
        }
    }
}

// ---------------- pooling ----------------
__global__ void k_zero_pool() {
    int i = blockIdx.x * blockDim.x + threadIdx.x;
    if (i < GG * 128) g_gsum[i] = 0.f;
    if (i < GG) g_gcnt[i] = 0.f;
}

__global__ __launch_bounds__(128) void k_pool(const int* __restrict__ batch, int n) {
    const int NPB = 512;
    int n0 = blockIdx.x * NPB;
    if (n0 >= n) return;
    int n1 = min(n0 + NPB, n);
    int d = threadIdx.x;  // 128 channels
    int cur = batch[n0];
    float acc = 0.f, cacc = 0.f;
    for (int nn = n0; nn < n1; nn++) {
        int g = batch[nn];
        if (g != cur) {
            atomicAdd(&g_gsum[cur * 128 + d], acc);
            if (d == 0) atomicAdd(&g_gcnt[cur], cacc);
            acc = 0.f; cacc = 0.f; cur = g;
        }
        acc += g_h2[nn * 128 + d];
        cacc += 1.f;
    }
    atomicAdd(&g_gsum[cur * 128 + d], acc);
    if (d == 0) atomicAdd(&g_gcnt[cur], cacc);
}

// ---------------- decoder: out[g] = (relu(gfeat@W1+b1))@W2 + b2 ----------
__global__ __launch_bounds__(64) void k_final(
    const float* __restrict__ W1, const float* __restrict__ b1,
    const float* __restrict__ W2, const float* __restrict__ b2,
    float* __restrict__ out) {
    int g = blockIdx.x;
    int c = threadIdx.x;  // 64
    __shared__ float sh[64];
    float inv = 1.f / fmaxf(g_gcnt[g], 1.f);
    float acc = 0.f;
#pragma unroll 4
    for (int k = 0; k < 128; k++) {
        float gf = g_gsum[g * 128 + k] * inv;
        acc += gf * W1[k * 64 + c];
    }
    acc = fmaxf(acc + b1[c], 0.f);
    sh[c] = acc * W2[c];
    __syncthreads();
    if (c < 32) {
        float v = sh[c] + sh[c + 32];
        for (int off = 16; off > 0; off >>= 1)
            v += __shfl_down_sync(0xffffffffu, v, off);
        if (c == 0) out[g] = v + b2[0];
    }
}

// ---------------- launch ----------------
extern "C" void kernel_launch(void* const* d_in, const int* in_sizes, int n_in,
                              void* d_out, int out_size) {
    const float* x       = (const float*)d_in[0];
    const int*   ei      = (const int*)d_in[1];
    const int*   batch   = (const int*)d_in[2];
    const float* conv_W  = (const float*)d_in[3];   // [4,64,64]
    const float* conv_b  = (const float*)d_in[4];   // [4,64]
    const float* bn_g    = (const float*)d_in[5];
    const float* bn_b    = (const float*)d_in[6];
    const float* bn_m    = (const float*)d_in[7];
    const float* bn_v    = (const float*)d_in[8];
    const float* enc_W1  = (const float*)d_in[9];   // [256,256]
    const float* enc_b1  = (const float*)d_in[10];  // [256]
    const float* enc_W2  = (const float*)d_in[11];  // [256,128]
    const float* enc_b2  = (const float*)d_in[12];  // [128]
    const float* dec_W1  = (const float*)d_in[13];  // [128,64]
    const float* dec_b1  = (const float*)d_in[14];  // [64]
    const float* dec_W2  = (const float*)d_in[15];  // [64,1]
    const float* dec_b2  = (const float*)d_in[16];  // [1]
    float* out = (float*)d_out;

    int n  = in_sizes[0] / 64;
    int ne = in_sizes[1] / 2;

    int nb1024 = (n + 1023) / 1024;
    int nb256  = (n + 255) / 256;
    int eb256  = (ne + 255) / 256;

    // GCN normalization + CSR build (once, reused by all 4 layers)
    k_init_cnt<<<nb256, 256>>>(n);
    k_deg<<<eb256, 256>>>(ei, ne);
    k_dis<<<nb256, 256>>>(n);
    k_scanA<<<nb1024, 1024>>>(n);
    k_scanB<<<1, 32>>>(nb1024);
    k_scanC<<<nb256, 256>>>(n, ne);
    k_scatter<<<eb256, 256>>>(ei, ne);

    // 4 GCN layers
    int convBlocks = (n + 63) / 64;
    int aggBlocks  = (n + 7) / 8;  // 8 warps per block
    for (int l = 0; l < 4; l++) {
        k_conv_gemm<<<convBlocks, 256>>>(x, conv_W + l * 64 * 64, n, l);
        k_agg<<<aggBlocks, 256>>>(n, l, conv_b + l * 64, bn_g + l * 64,
                                  bn_b + l * 64, bn_m + l * 64, bn_v + l * 64);
    }

    // encoder MLP
    dim3 g1((n + 127) / 128, 2);
    k_enc_gemm<<<g1, 256>>>(enc_W1, enc_b1, 256, 256, 0, n);
    dim3 g2((n + 127) / 128, 1);
    k_enc_gemm<<<g2, 256>>>(enc_W2, enc_b2, 256, 128, 1, n);

    // pooling + decoder
    k_zero_pool<<<(GG * 128 + 255) / 256, 256>>>();
    k_pool<<<(n + 511) / 512, 128>>>(batch, n);
    k_final<<<GG, 64>>>(dec_W1, dec_b1, dec_W2, dec_b2, out);
}

// round 4
// speedup vs baseline: 1.6596x; 1.6596x over previous
#include <cuda_runtime.h>
#include <cstdint>

// ---------------- problem constants ----------------
#define NN 100000
#define NE 3200000
#define GG 64

// ---------------- f32x2 packed FMA helpers (sm_100+ only, via PTX) --------
#define FMA_F32X2(d, a, b) \
    asm("fma.rn.f32x2 %0, %1, %2, %0;" : "+l"(d) : "l"(a), "l"(b))

__device__ __forceinline__ uint64_t dup_f32(float x) {
    uint64_t d;
    uint32_t u = __float_as_uint(x);
    asm("mov.b64 %0, {%1, %1};" : "=l"(d) : "r"(u));
    return d;
}

__device__ __forceinline__ void unpack_f32x2(uint64_t v, float& lo, float& hi) {
    uint32_t a, b;
    asm("mov.b64 {%0, %1}, %2;" : "=r"(a), "=r"(b) : "l"(v));
    lo = __uint_as_float(a);
    hi = __uint_as_float(b);
}

// ---------------- device scratch (no allocs allowed) ----------------
__device__ float g_y[NN * 64];          // dis-scaled x@W
__device__ float g_local[NN * 256];     // concat of 4 layer outputs
__device__ float g_h1[NN * 256];        // enc layer-1 output
__device__ float g_h2[NN * 128];        // enc layer-2 output
__device__ float g_dis[NN];
__device__ int   g_cnt[NN];
__device__ int   g_rs[NN];              // CSR segment start
__device__ int   g_re[NN];              // CSR segment end
__device__ int   g_woff[NN];
__device__ int   g_src[NE];
__device__ int   g_total;
__device__ float g_gsum[GG * 128];
__device__ float g_gcnt[GG];

// ---------------- init: cnt=1 (self loop), zero pool + alloc counter ------
__global__ void k_init(int n) {
    int i = blockIdx.x * blockDim.x + threadIdx.x;
    if (i < n) g_cnt[i] = 1;
    if (i < GG * 128) g_gsum[i] = 0.f;
    if (i < GG) g_gcnt[i] = 0.f;
    if (i == 0) g_total = 0;
}

__global__ void k_deg(const int* __restrict__ ei, int ne) {
    int i = blockIdx.x * blockDim.x + threadIdx.x;
    if (i < ne) atomicAdd(&g_cnt[ei[ne + i]], 1);  // col = target
}

// dis + CSR segment allocation (order of segments irrelevant — sums commute)
__global__ void k_alloc(int n) {
    int i = blockIdx.x * blockDim.x + threadIdx.x;
    if (i < n) {
        int cnt = g_cnt[i];
        g_dis[i] = rsqrtf((float)cnt);
        int indeg = cnt - 1;
        int start = atomicAdd(&g_total, indeg);
        g_rs[i] = start;
        g_re[i] = start + indeg;
        g_woff[i] = start;
    }
}

__global__ void k_scatter(const int* __restrict__ ei, int ne) {
    int i = blockIdx.x * blockDim.x + threadIdx.x;
    if (i < ne) {
        int c = ei[ne + i];
        int pos = atomicAdd(&g_woff[c], 1);
        g_src[pos] = ei[i];  // row = source
    }
}

// ---------------- conv GEMM: y = (Xin @ W_l) * dis[row] ----------------
// block: 64 rows x 64 cols, 256 threads, 4x4 per thread (f32x2 packed)
__global__ __launch_bounds__(256) void k_conv_gemm(
    const float* __restrict__ X0, const float* __restrict__ W,
    int n, int layer) {
    __shared__ float As[64][65];
    __shared__ float Ws[64][64];
    int tid = threadIdx.x;
    int rowBase = blockIdx.x * 64;

    for (int idx = tid; idx < 4096; idx += 256)
        Ws[idx >> 6][idx & 63] = W[idx];
    for (int idx = tid; idx < 4096; idx += 256) {
        int r = idx >> 6, k = idx & 63;
        int gr = rowBase + r;
        float v = 0.f;
        if (gr < n) {
            if (layer == 0) v = X0[gr * 64 + k];
            else            v = g_local[gr * 256 + (layer - 1) * 64 + k];
        }
        As[r][k] = v;
    }
    __syncthreads();

    int tx = tid & 15, ty = tid >> 4;
    int c4 = tx * 4, r0 = ty * 4;
    uint64_t acc2[4][2] = {};
#pragma unroll
    for (int k = 0; k < 64; k++) {
        ulonglong2 bq = *(const ulonglong2*)&Ws[k][c4];  // pairs (c,c+1),(c+2,c+3)
#pragma unroll
        for (int i = 0; i < 4; i++) {
            uint64_t ad = dup_f32(As[r0 + i][k]);
            FMA_F32X2(acc2[i][0], ad, bq.x);
            FMA_F32X2(acc2[i][1], ad, bq.y);
        }
    }
#pragma unroll
    for (int i = 0; i < 4; i++) {
        int gr = rowBase + r0 + i;
        if (gr < n) {
            float d = g_dis[gr];
            float4 v;
            unpack_f32x2(acc2[i][0], v.x, v.y);
            unpack_f32x2(acc2[i][1], v.z, v.w);
            v.x *= d; v.y *= d; v.z *= d; v.w *= d;
            *(float4*)&g_y[gr * 64 + c4] = v;
        }
    }
}

// ---------------- aggregation + BN + relu + skip ----------
// one node per warp; lanes 0-15 handle even edges, 16-31 odd edges,
// each lane gathers float4 (16 lanes x 16B = full 64-float row).
__global__ __launch_bounds__(256) void k_agg(
    int n, int layer,
    const float* __restrict__ bias, const float* __restrict__ gamma,
    const float* __restrict__ beta, const float* __restrict__ mean,
    const float* __restrict__ var) {
    int warp = (blockIdx.x * blockDim.x + threadIdx.x) >> 5;
    int lane = threadIdx.x & 31;
    if (warp >= n) return;
    int c = warp;
    int half = lane >> 4;
    int l16 = lane & 15;
    const float4* y4 = (const float4*)g_y;

    float4 acc;
    if (half == 0) {
        acc = y4[c * 16 + l16];  // self loop counted once
    } else {
        acc.x = 0.f; acc.y = 0.f; acc.z = 0.f; acc.w = 0.f;
    }
    int s = g_rs[c], e = g_re[c];
    for (int i = s + half; i < e; i += 2) {
        int r = g_src[i];
        float4 v = y4[r * 16 + l16];
        acc.x += v.x; acc.y += v.y; acc.z += v.z; acc.w += v.w;
    }
    // combine the two halves (lane <-> lane^16 hold same channels)
    acc.x += __shfl_xor_sync(0xffffffffu, acc.x, 16);
    acc.y += __shfl_xor_sync(0xffffffffu, acc.y, 16);
    acc.z += __shfl_xor_sync(0xffffffffu, acc.z, 16);
    acc.w += __shfl_xor_sync(0xffffffffu, acc.w, 16);

    if (half == 0) {
        float dc = g_dis[c];
        int d0 = l16 * 4;
        float4 ga = *(const float4*)&gamma[d0];
        float4 va = *(const float4*)&var[d0];
        float4 bi = *(const float4*)&bias[d0];
        float4 me = *(const float4*)&mean[d0];
        float4 be = *(const float4*)&beta[d0];
        float4 v;
        v.x = fmaxf((acc.x * dc + bi.x - me.x) * (ga.x * rsqrtf(va.x + 1e-5f)) + be.x, 0.f);
        v.y = fmaxf((acc.y * dc + bi.y - me.y) * (ga.y * rsqrtf(va.y + 1e-5f)) + be.y, 0.f);
        v.z = fmaxf((acc.z * dc + bi.z - me.z) * (ga.z * rsqrtf(va.z + 1e-5f)) + be.z, 0.f);
        v.w = fmaxf((acc.w * dc + bi.w - me.w) * (ga.w * rsqrtf(va.w + 1e-5f)) + be.w, 0.f);
        if (layer == 2) {  // skip: += previous_outputs[0] (cols 0..63)
            float4 pv = *(const float4*)&g_local[c * 256 + d0];
            v.x += pv.x; v.y += pv.y; v.z += pv.z; v.w += pv.w;
        }
        *(float4*)&g_local[c * 256 + layer * 64 + d0] = v;
    }
}

// ---------------- encoder GEMMs: out = relu(A @ B + bias) ----------------
// BM=128, BN=128, BK=16; 256 threads; 8x8 per thread, f32x2 packed over N.
// mode 0: A=g_local (ld 256), out=g_h1 (ld 256)
// mode 1: A=g_h1    (ld 256), out=g_h2 (ld 128)
__global__ __launch_bounds__(256) void k_enc_gemm(
    const float* __restrict__ B, const float* __restrict__ bias,
    int K, int ncols, int mode, int n) {
    __shared__ float As[128][17];
    __shared__ float Bs[16][128];
    const float* A = (mode == 0) ? g_local : g_h1;
    float* O = (mode == 0) ? g_h1 : g_h2;
    const int lda = 256;
    const int ldo = (mode == 0) ? 256 : 128;
    int rowBase = blockIdx.x * 128;
    int colBase = blockIdx.y * 128;
    int tid = threadIdx.x;
    int tx = tid & 15, ty = tid >> 4;
    uint64_t acc2[8][4] = {};  // pairs over N

    for (int kb = 0; kb < K; kb += 16) {
        for (int idx = tid; idx < 128 * 16; idx += 256) {
            int r = idx >> 4, k = idx & 15;
            int gr = rowBase + r;
            As[r][k] = (gr < n) ? A[gr * lda + kb + k] : 0.f;
        }
        for (int idx = tid; idx < 16 * 128; idx += 256) {
            int r = idx >> 7, cc = idx & 127;
            Bs[r][cc] = B[(kb + r) * ncols + colBase + cc];
        }
        __syncthreads();
#pragma unroll
        for (int k = 0; k < 16; k++) {
            ulonglong2 bq0 = *(const ulonglong2*)&Bs[k][tx * 8];
            ulonglong2 bq1 = *(const ulonglong2*)&Bs[k][tx * 8 + 4];
#pragma unroll
            for (int i = 0; i < 8; i++) {
                uint64_t ad = dup_f32(As[ty * 8 + i][k]);
                FMA_F32X2(acc2[i][0], ad, bq0.x);
                FMA_F32X2(acc2[i][1], ad, bq0.y);
                FMA_F32X2(acc2[i][2], ad, bq1.x);
                FMA_F32X2(acc2[i][3], ad, bq1.y);
            }
        }
        __syncthreads();
    }
    int cb = colBase + tx * 8;
    float4 bb0 = *(const float4*)&bias[cb];
    float4 bb1 = *(const float4*)&bias[cb + 4];
#pragma unroll
    for (int i = 0; i < 8; i++) {
        int gr = rowBase + ty * 8 + i;
        if (gr < n) {
            float4 v0, v1;
            unpack_f32x2(acc2[i][0], v0.x, v0.y);
            unpack_f32x2(acc2[i][1], v0.z, v0.w);
            unpack_f32x2(acc2[i][2], v1.x, v1.y);
            unpack_f32x2(acc2[i][3], v1.z, v1.w);
            v0.x = fmaxf(v0.x + bb0.x, 0.f);
            v0.y = fmaxf(v0.y + bb0.y, 0.f);
            v0.z = fmaxf(v0.z + bb0.z, 0.f);
            v0.w = fmaxf(v0.w + bb0.w, 0.f);
            v1.x = fmaxf(v1.x + bb1.x, 0.f);
            v1.y = fmaxf(v1.y + bb1.y, 0.f);
            v1.z = fmaxf(v1.z + bb1.z, 0.f);
            v1.w = fmaxf(v1.w + bb1.w, 0.f);
            *(float4*)&O[gr * ldo + cb] = v0;
            *(float4*)&O[gr * ldo + cb + 4] = v1;
        }
    }
}

// ---------------- pooling ----------------
__global__ __launch_bounds__(128) void k_pool(const int* __restrict__ batch, int n) {
    const int NPB = 512;
    int n0 = blockIdx.x * NPB;
    if (n0 >= n) return;
    int n1 = min(n0 + NPB, n);
    int d = threadIdx.x;  // 128 channels
    int cur = batch[n0];
    float acc = 0.f, cacc = 0.f;
    for (int nn = n0; nn < n1; nn++) {
        int g = batch[nn];
        if (g != cur) {
            atomicAdd(&g_gsum[cur * 128 + d], acc);
            if (d == 0) atomicAdd(&g_gcnt[cur], cacc);
            acc = 0.f; cacc = 0.f; cur = g;
        }
        acc += g_h2[nn * 128 + d];
        cacc += 1.f;
    }
    atomicAdd(&g_gsum[cur * 128 + d], acc);
    if (d == 0) atomicAdd(&g_gcnt[cur], cacc);
}

// ---------------- decoder: out[g] = (relu(gfeat@W1+b1))@W2 + b2 ----------
__global__ __launch_bounds__(64) void k_final(
    const float* __restrict__ W1, const float* __restrict__ b1,
    const float* __restrict__ W2, const float* __restrict__ b2,
    float* __restrict__ out) {
    int g = blockIdx.x;
    int c = threadIdx.x;  // 64
    __shared__ float sh[64];
    float inv = 1.f / fmaxf(g_gcnt[g], 1.f);
    float acc = 0.f;
#pragma unroll 4
    for (int k = 0; k < 128; k++) {
        float gf = g_gsum[g * 128 + k] * inv;
        acc += gf * W1[k * 64 + c];
    }
    acc = fmaxf(acc + b1[c], 0.f);
    sh[c] = acc * W2[c];
    __syncthreads();
    if (c < 32) {
        float v = sh[c] + sh[c + 32];
        for (int off = 16; off > 0; off >>= 1)
            v += __shfl_down_sync(0xffffffffu, v, off);
        if (c == 0) out[g] = v + b2[0];
    }
}

// ---------------- launch ----------------
extern "C" void kernel_launch(void* const* d_in, const int* in_sizes, int n_in,
                              void* d_out, int out_size) {
    const float* x       = (const float*)d_in[0];
    const int*   ei      = (const int*)d_in[1];
    const int*   batch   = (const int*)d_in[2];
    const float* conv_W  = (const float*)d_in[3];   // [4,64,64]
    const float* conv_b  = (const float*)d_in[4];   // [4,64]
    const float* bn_g    = (const float*)d_in[5];
    const float* bn_b    = (const float*)d_in[6];
    const float* bn_m    = (const float*)d_in[7];
    const float* bn_v    = (const float*)d_in[8];
    const float* enc_W1  = (const float*)d_in[9];   // [256,256]
    const float* enc_b1  = (const float*)d_in[10];  // [256]
    const float* enc_W2  = (const float*)d_in[11];  // [256,128]
    const float* enc_b2  = (const float*)d_in[12];  // [128]
    const float* dec_W1  = (const float*)d_in[13];  // [128,64]
    const float* dec_b1  = (const float*)d_in[14];  // [64]
    const float* dec_W2  = (const float*)d_in[15];  // [64,1]
    const float* dec_b2  = (const float*)d_in[16];  // [1]
    float* out = (float*)d_out;

    int n  = in_sizes[0] / 64;
    int ne = in_sizes[1] / 2;

    int nb256 = (n + 255) / 256;
    int eb256 = (ne + 255) / 256;

    int convBlocks = (n + 63) / 64;
    int aggBlocks  = (n + 7) / 8;  // 8 warps per block

    // CSR build via atomic allocation (order within a segment is irrelevant)
    k_init<<<nb256, 256>>>(n);                          // launch 0
    k_deg<<<eb256, 256>>>(ei, ne);                      // launch 1
    k_alloc<<<nb256, 256>>>(n);                         // launch 2
    k_conv_gemm<<<convBlocks, 256>>>(x, conv_W, n, 0);  // launch 3 (profiled?)
    k_scatter<<<eb256, 256>>>(ei, ne);                  // launch 4
    k_agg<<<aggBlocks, 256>>>(n, 0, conv_b, bn_g, bn_b, bn_m, bn_v);  // launch 5

    for (int l = 1; l < 4; l++) {
        k_conv_gemm<<<convBlocks, 256>>>(x, conv_W + l * 64 * 64, n, l);
        k_agg<<<aggBlocks, 256>>>(n, l, conv_b + l * 64, bn_g + l * 64,
                                  bn_b + l * 64, bn_m + l * 64, bn_v + l * 64);
    }

    // encoder MLP
    dim3 g1((n + 127) / 128, 2);
    k_enc_gemm<<<g1, 256>>>(enc_W1, enc_b1, 256, 256, 0, n);
    dim3 g2((n + 127) / 128, 1);
    k_enc_gemm<<<g2, 256>>>(enc_W2, enc_b2, 256, 128, 1, n);

    // pooling + decoder
    k_pool<<<(n + 511) / 512, 128>>>(batch, n);
    k_final<<<GG, 64>>>(dec_W1, dec_b1, dec_W2, dec_b2, out);
}

// round 5
// speedup vs baseline: 2.1900x; 1.3196x over previous
#include <cuda_runtime.h>
#include <cuda_bf16.h>
#include <cstdint>

// ---------------- problem constants ----------------
#define NN 100000
#define NE 3200000
#define GG 64

// ---------------- f32x2 packed FMA helpers (sm_100+ only, via PTX) --------
#define FMA_F32X2(d, a, b) \
    asm("fma.rn.f32x2 %0, %1, %2, %0;" : "+l"(d) : "l"(a), "l"(b))

__device__ __forceinline__ uint64_t dup_f32(float x) {
    uint64_t d;
    uint32_t u = __float_as_uint(x);
    asm("mov.b64 %0, {%1, %1};" : "=l"(d) : "r"(u));
    return d;
}

__device__ __forceinline__ void unpack_f32x2(uint64_t v, float& lo, float& hi) {
    uint32_t a, b;
    asm("mov.b64 {%0, %1}, %2;" : "=r"(a), "=r"(b) : "l"(v));
    lo = __uint_as_float(a);
    hi = __uint_as_float(b);
}

// ---------------- mma.sync helpers ----------------
__device__ __forceinline__ uint32_t smem_u32(const void* p) {
    uint32_t a;
    asm("{ .reg .u64 t; cvta.to.shared.u64 t, %1; cvt.u32.u64 %0, t; }"
        : "=r"(a) : "l"(p));
    return a;
}

__device__ __forceinline__ void ldsm_x4(uint32_t& r0, uint32_t& r1,
                                        uint32_t& r2, uint32_t& r3,
                                        uint32_t addr) {
    asm volatile("ldmatrix.sync.aligned.m8n8.x4.shared.b16 {%0,%1,%2,%3}, [%4];"
                 : "=r"(r0), "=r"(r1), "=r"(r2), "=r"(r3) : "r"(addr));
}

__device__ __forceinline__ void mma_bf16(float* d, const uint32_t* a,
                                         const uint32_t* b) {
    asm volatile(
        "mma.sync.aligned.m16n8k16.row.col.f32.bf16.bf16.f32 "
        "{%0,%1,%2,%3}, {%4,%5,%6,%7}, {%8,%9}, {%0,%1,%2,%3};"
        : "+f"(d[0]), "+f"(d[1]), "+f"(d[2]), "+f"(d[3])
        : "r"(a[0]), "r"(a[1]), "r"(a[2]), "r"(a[3]), "r"(b[0]), "r"(b[1]));
}

// ---------------- device scratch (no allocs allowed) ----------------
__device__ float g_y[NN * 64];          // dis-scaled x@W
__device__ float g_local[NN * 256];     // concat of 4 layer outputs
__device__ float g_h1[NN * 256];        // enc layer-1 output
__device__ float g_h2[NN * 128];        // enc layer-2 output
__device__ float g_dis[NN];
__device__ int   g_cnt[NN];
__device__ int   g_rs[NN];              // CSR segment start
__device__ int   g_re[NN];              // CSR segment end
__device__ int   g_woff[NN];
__device__ int   g_src[NE];
__device__ int   g_total;
__device__ float g_gsum[GG * 128];
__device__ float g_gcnt[GG];
// pre-split, pre-transposed (n-major) encoder weights
__device__ __nv_bfloat16 g_w1h[256 * 256];
__device__ __nv_bfloat16 g_w1l[256 * 256];
__device__ __nv_bfloat16 g_w2h[128 * 256];
__device__ __nv_bfloat16 g_w2l[128 * 256];

// ---------------- init: cnt=1 (self loop), zero pool + alloc counter ------
__global__ void k_init(int n) {
    int i = blockIdx.x * blockDim.x + threadIdx.x;
    if (i < n) g_cnt[i] = 1;
    if (i < GG * 128) g_gsum[i] = 0.f;
    if (i < GG) g_gcnt[i] = 0.f;
    if (i == 0) g_total = 0;
}

__global__ void k_deg(const int* __restrict__ ei, int ne) {
    int i = blockIdx.x * blockDim.x + threadIdx.x;
    if (i < ne) atomicAdd(&g_cnt[ei[ne + i]], 1);  // col = target
}

// dis + CSR segment allocation (order of segments irrelevant — sums commute)
__global__ void k_alloc(int n) {
    int i = blockIdx.x * blockDim.x + threadIdx.x;
    if (i < n) {
        int cnt = g_cnt[i];
        g_dis[i] = rsqrtf((float)cnt);
        int indeg = cnt - 1;
        int start = atomicAdd(&g_total, indeg);
        g_rs[i] = start;
        g_re[i] = start + indeg;
        g_woff[i] = start;
    }
}

__global__ void k_scatter(const int* __restrict__ ei, int ne) {
    int i = blockIdx.x * blockDim.x + threadIdx.x;
    if (i < ne) {
        int c = ei[ne + i];
        int pos = atomicAdd(&g_woff[c], 1);
        g_src[pos] = ei[i];  // row = source
    }
}

// ---------------- weight split+transpose (k-major -> n-major, hi/lo bf16) --
__global__ void k_split_w(const float* __restrict__ W1,
                          const float* __restrict__ W2) {
    int idx = blockIdx.x * blockDim.x + threadIdx.x;
    if (idx < 256 * 256) {
        int nn = idx >> 8, kk = idx & 255;
        float v = W1[kk * 256 + nn];
        __nv_bfloat16 h = __float2bfloat16(v);
        g_w1h[idx] = h;
        g_w1l[idx] = __float2bfloat16(v - __bfloat162float(h));
    }
    if (idx < 128 * 256) {
        int nn = idx >> 8, kk = idx & 255;
        float v = W2[kk * 128 + nn];
        __nv_bfloat16 h = __float2bfloat16(v);
        g_w2h[idx] = h;
        g_w2l[idx] = __float2bfloat16(v - __bfloat162float(h));
    }
}

// ---------------- conv GEMM: y = (Xin @ W_l) * dis[row] ----------------
// block: 64 rows x 64 cols, 256 threads, 4x4 per thread (f32x2 packed)
__global__ __launch_bounds__(256) void k_conv_gemm(
    const float* __restrict__ X0, const float* __restrict__ W,
    int n, int layer) {
    __shared__ float As[64][65];
    __shared__ float Ws[64][64];
    int tid = threadIdx.x;
    int rowBase = blockIdx.x * 64;

    for (int idx = tid; idx < 4096; idx += 256)
        Ws[idx >> 6][idx & 63] = W[idx];
    for (int idx = tid; idx < 4096; idx += 256) {
        int r = idx >> 6, k = idx & 63;
        int gr = rowBase + r;
        float v = 0.f;
        if (gr < n) {
            if (layer == 0) v = X0[gr * 64 + k];
            else            v = g_local[gr * 256 + (layer - 1) * 64 + k];
        }
        As[r][k] = v;
    }
    __syncthreads();

    int tx = tid & 15, ty = tid >> 4;
    int c4 = tx * 4, r0 = ty * 4;
    uint64_t acc2[4][2] = {};
#pragma unroll
    for (int k = 0; k < 64; k++) {
        ulonglong2 bq = *(const ulonglong2*)&Ws[k][c4];
#pragma unroll
        for (int i = 0; i < 4; i++) {
            uint64_t ad = dup_f32(As[r0 + i][k]);
            FMA_F32X2(acc2[i][0], ad, bq.x);
            FMA_F32X2(acc2[i][1], ad, bq.y);
        }
    }
#pragma unroll
    for (int i = 0; i < 4; i++) {
        int gr = rowBase + r0 + i;
        if (gr < n) {
            float d = g_dis[gr];
            float4 v;
            unpack_f32x2(acc2[i][0], v.x, v.y);
            unpack_f32x2(acc2[i][1], v.z, v.w);
            v.x *= d; v.y *= d; v.z *= d; v.w *= d;
            *(float4*)&g_y[gr * 64 + c4] = v;
        }
    }
}

// ---------------- aggregation + BN + relu + skip ----------
__global__ __launch_bounds__(256) void k_agg(
    int n, int layer,
    const float* __restrict__ bias, const float* __restrict__ gamma,
    const float* __restrict__ beta, const float* __restrict__ mean,
    const float* __restrict__ var) {
    int warp = (blockIdx.x * blockDim.x + threadIdx.x) >> 5;
    int lane = threadIdx.x & 31;
    if (warp >= n) return;
    int c = warp;
    int half = lane >> 4;
    int l16 = lane & 15;
    const float4* y4 = (const float4*)g_y;

    float4 acc;
    if (half == 0) {
        acc = y4[c * 16 + l16];  // self loop counted once
    } else {
        acc.x = 0.f; acc.y = 0.f; acc.z = 0.f; acc.w = 0.f;
    }
    int s = g_rs[c], e = g_re[c];
    for (int i = s + half; i < e; i += 2) {
        int r = g_src[i];
        float4 v = y4[r * 16 + l16];
        acc.x += v.x; acc.y += v.y; acc.z += v.z; acc.w += v.w;
    }
    acc.x += __shfl_xor_sync(0xffffffffu, acc.x, 16);
    acc.y += __shfl_xor_sync(0xffffffffu, acc.y, 16);
    acc.z += __shfl_xor_sync(0xffffffffu, acc.z, 16);
    acc.w += __shfl_xor_sync(0xffffffffu, acc.w, 16);

    if (half == 0) {
        float dc = g_dis[c];
        int d0 = l16 * 4;
        float4 ga = *(const float4*)&gamma[d0];
        float4 va = *(const float4*)&var[d0];
        float4 bi = *(const float4*)&bias[d0];
        float4 me = *(const float4*)&mean[d0];
        float4 be = *(const float4*)&beta[d0];
        float4 v;
        v.x = fmaxf((acc.x * dc + bi.x - me.x) * (ga.x * rsqrtf(va.x + 1e-5f)) + be.x, 0.f);
        v.y = fmaxf((acc.y * dc + bi.y - me.y) * (ga.y * rsqrtf(va.y + 1e-5f)) + be.y, 0.f);
        v.z = fmaxf((acc.z * dc + bi.z - me.z) * (ga.z * rsqrtf(va.z + 1e-5f)) + be.z, 0.f);
        v.w = fmaxf((acc.w * dc + bi.w - me.w) * (ga.w * rsqrtf(va.w + 1e-5f)) + be.w, 0.f);
        if (layer == 2) {
            float4 pv = *(const float4*)&g_local[c * 256 + d0];
            v.x += pv.x; v.y += pv.y; v.z += pv.z; v.w += pv.w;
        }
        *(float4*)&g_local[c * 256 + layer * 64 + d0] = v;
    }
}

// ---------------- encoder GEMM via mma.sync (bf16 split x3) ----------------
// BM=128, BN=64, BK=32; 256 threads; warp tile 32x32.
// mode 0: A=g_local (ld 256), W=g_w1*, out=g_h1 (ld 256)
// mode 1: A=g_h1    (ld 256), W=g_w2*, out=g_h2 (ld 128)
#define EPITCH 40  // bf16 elems per smem row (32 + 8 pad) => 80B, conflict-free ldmatrix
__global__ __launch_bounds__(256) void k_enc_mma(
    const float* __restrict__ bias, int mode, int n) {
    __shared__ __nv_bfloat16 Ah[128 * EPITCH];
    __shared__ __nv_bfloat16 Al[128 * EPITCH];
    __shared__ __nv_bfloat16 Bh[64 * EPITCH];
    __shared__ __nv_bfloat16 Bl[64 * EPITCH];

    const float* A = (mode == 0) ? g_local : g_h1;
    float* O = (mode == 0) ? g_h1 : g_h2;
    const __nv_bfloat16* Wh = (mode == 0) ? g_w1h : g_w2h;
    const __nv_bfloat16* Wl = (mode == 0) ? g_w1l : g_w2l;
    const int lda = 256;
    const int ldo = (mode == 0) ? 256 : 128;
    const int K = 256;

    int rowBase = blockIdx.x * 128;
    int colBase = blockIdx.y * 64;
    int tid = threadIdx.x;
    int warp = tid >> 5, lane = tid & 31;
    int m0 = (warp >> 1) * 32;  // warp M offset in tile
    int n0 = (warp & 1) * 32;   // warp N offset in tile

    float acc[2][4][4];
#pragma unroll
    for (int mt = 0; mt < 2; mt++)
#pragma unroll
        for (int nt = 0; nt < 4; nt++)
#pragma unroll
            for (int q = 0; q < 4; q++) acc[mt][nt][q] = 0.f;

    uint32_t ah_base = smem_u32(Ah);
    uint32_t al_base = smem_u32(Al);
    uint32_t bh_base = smem_u32(Bh);
    uint32_t bl_base = smem_u32(Bl);

    for (int kb = 0; kb < K; kb += 32) {
        // load+split A: 128 rows x 32 cols fp32
#pragma unroll
        for (int c = 0; c < 4; c++) {
            int idx = tid + c * 256;       // 0..1023
            int r = idx >> 3, f4 = idx & 7;
            int gr = rowBase + r;
            float4 v = make_float4(0.f, 0.f, 0.f, 0.f);
            if (gr < n) v = *(const float4*)&A[gr * lda + kb + f4 * 4];
            __nv_bfloat16 hx = __float2bfloat16(v.x);
            __nv_bfloat16 hy = __float2bfloat16(v.y);
            __nv_bfloat16 hz = __float2bfloat16(v.z);
            __nv_bfloat16 hw = __float2bfloat16(v.w);
            __nv_bfloat162 h01 = {hx, hy}, h23 = {hz, hw};
            __nv_bfloat162 l01 = {__float2bfloat16(v.x - __bfloat162float(hx)),
                                  __float2bfloat16(v.y - __bfloat162float(hy))};
            __nv_bfloat162 l23 = {__float2bfloat16(v.z - __bfloat162float(hz)),
                                  __float2bfloat16(v.w - __bfloat162float(hw))};
            int off = r * EPITCH + f4 * 4;
            *(__nv_bfloat162*)&Ah[off] = h01;
            *(__nv_bfloat162*)&Ah[off + 2] = h23;
            *(__nv_bfloat162*)&Al[off] = l01;
            *(__nv_bfloat162*)&Al[off + 2] = l23;
        }
        // load B tiles (pre-split, n-major): 64 rows x 32 cols bf16
        {
            int r = tid >> 2, q = tid & 3;  // 64 rows x 4 chunks of 8 bf16
            const uint4* srcH = (const uint4*)&Wh[(colBase + r) * K + kb + q * 8];
            const uint4* srcL = (const uint4*)&Wl[(colBase + r) * K + kb + q * 8];
            uint4 vh = *srcH;
            uint4 vl = *srcL;
            int off = r * EPITCH + q * 8;
            *(uint4*)&Bh[off] = vh;
            *(uint4*)&Bl[off] = vl;
        }
        __syncthreads();

#pragma unroll
        for (int ks = 0; ks < 2; ks++) {
            int k0 = ks * 16;
            // A fragments (hi/lo) for 2 m-tiles
            uint32_t aH[2][4], aL[2][4];
#pragma unroll
            for (int mt = 0; mt < 2; mt++) {
                int row = m0 + mt * 16 + (lane & 15);
                int kc = k0 + (lane >> 4) * 8;
                uint32_t byteoff = (uint32_t)(row * EPITCH + kc) * 2;
                ldsm_x4(aH[mt][0], aH[mt][1], aH[mt][2], aH[mt][3], ah_base + byteoff);
                ldsm_x4(aL[mt][0], aL[mt][1], aL[mt][2], aL[mt][3], al_base + byteoff);
            }
            // B fragments (hi/lo) for 4 n-tiles (2 per x4)
            uint32_t bH[4][2], bL[4][2];
#pragma unroll
            for (int ng = 0; ng < 2; ng++) {
                int rrow = n0 + ng * 16 + (lane & 7) + ((lane >> 4) & 1) * 8;
                int kc = k0 + ((lane >> 3) & 1) * 8;
                uint32_t byteoff = (uint32_t)(rrow * EPITCH + kc) * 2;
                uint32_t r0, r1, r2, r3;
                ldsm_x4(r0, r1, r2, r3, bh_base + byteoff);
                bH[ng * 2][0] = r0; bH[ng * 2][1] = r1;
                bH[ng * 2 + 1][0] = r2; bH[ng * 2 + 1][1] = r3;
                ldsm_x4(r0, r1, r2, r3, bl_base + byteoff);
                bL[ng * 2][0] = r0; bL[ng * 2][1] = r1;
                bL[ng * 2 + 1][0] = r2; bL[ng * 2 + 1][1] = r3;
            }
            // 3-term split MMA: hi*hi + hi*lo + lo*hi
#pragma unroll
            for (int mt = 0; mt < 2; mt++)
#pragma unroll
                for (int nt = 0; nt < 4; nt++) {
                    mma_bf16(acc[mt][nt], aH[mt], bH[nt]);
                    mma_bf16(acc[mt][nt], aH[mt], bL[nt]);
                    mma_bf16(acc[mt][nt], aL[mt], bH[nt]);
                }
        }
        __syncthreads();
    }

    // epilogue: bias + relu
#pragma unroll
    for (int mt = 0; mt < 2; mt++)
#pragma unroll
        for (int nt = 0; nt < 4; nt++) {
            int gn = colBase + n0 + nt * 8 + 2 * (lane & 3);
            float2 bb = *(const float2*)&bias[gn];
            int gm0 = rowBase + m0 + mt * 16 + (lane >> 2);
            if (gm0 < n) {
                float2 v = {fmaxf(acc[mt][nt][0] + bb.x, 0.f),
                            fmaxf(acc[mt][nt][1] + bb.y, 0.f)};
                *(float2*)&O[gm0 * ldo + gn] = v;
            }
            int gm1 = gm0 + 8;
            if (gm1 < n) {
                float2 v = {fmaxf(acc[mt][nt][2] + bb.x, 0.f),
                            fmaxf(acc[mt][nt][3] + bb.y, 0.f)};
                *(float2*)&O[gm1 * ldo + gn] = v;
            }
        }
}

// ---------------- pooling ----------------
__global__ __launch_bounds__(128) void k_pool(const int* __restrict__ batch, int n) {
    const int NPB = 512;
    int n0 = blockIdx.x * NPB;
    if (n0 >= n) return;
    int n1 = min(n0 + NPB, n);
    int d = threadIdx.x;  // 128 channels
    int cur = batch[n0];
    float acc = 0.f, cacc = 0.f;
    for (int nn = n0; nn < n1; nn++) {
        int g = batch[nn];
        if (g != cur) {
            atomicAdd(&g_gsum[cur * 128 + d], acc);
            if (d == 0) atomicAdd(&g_gcnt[cur], cacc);
            acc = 0.f; cacc = 0.f; cur = g;
        }
        acc += g_h2[nn * 128 + d];
        cacc += 1.f;
    }
    atomicAdd(&g_gsum[cur * 128 + d], acc);
    if (d == 0) atomicAdd(&g_gcnt[cur], cacc);
}

// ---------------- decoder: out[g] = (relu(gfeat@W1+b1))@W2 + b2 ----------
__global__ __launch_bounds__(64) void k_final(
    const float* __restrict__ W1, const float* __restrict__ b1,
    const float* __restrict__ W2, const float* __restrict__ b2,
    float* __restrict__ out) {
    int g = blockIdx.x;
    int c = threadIdx.x;  // 64
    __shared__ float sh[64];
    float inv = 1.f / fmaxf(g_gcnt[g], 1.f);
    float acc = 0.f;
#pragma unroll 4
    for (int k = 0; k < 128; k++) {
        float gf = g_gsum[g * 128 + k] * inv;
        acc += gf * W1[k * 64 + c];
    }
    acc = fmaxf(acc + b1[c], 0.f);
    sh[c] = acc * W2[c];
    __syncthreads();
    if (c < 32) {
        float v = sh[c] + sh[c + 32];
        for (int off = 16; off > 0; off >>= 1)
            v += __shfl_down_sync(0xffffffffu, v, off);
        if (c == 0) out[g] = v + b2[0];
    }
}

// ---------------- launch ----------------
extern "C" void kernel_launch(void* const* d_in, const int* in_sizes, int n_in,
                              void* d_out, int out_size) {
    const float* x       = (const float*)d_in[0];
    const int*   ei      = (const int*)d_in[1];
    const int*   batch   = (const int*)d_in[2];
    const float* conv_W  = (const float*)d_in[3];   // [4,64,64]
    const float* conv_b  = (const float*)d_in[4];   // [4,64]
    const float* bn_g    = (const float*)d_in[5];
    const float* bn_b    = (const float*)d_in[6];
    const float* bn_m    = (const float*)d_in[7];
    const float* bn_v    = (const float*)d_in[8];
    const float* enc_W1  = (const float*)d_in[9];   // [256,256]
    const float* enc_b1  = (const float*)d_in[10];  // [256]
    const float* enc_W2  = (const float*)d_in[11];  // [256,128]
    const float* enc_b2  = (const float*)d_in[12];  // [128]
    const float* dec_W1  = (const float*)d_in[13];  // [128,64]
    const float* dec_b1  = (const float*)d_in[14];  // [64]
    const float* dec_W2  = (const float*)d_in[15];  // [64,1]
    const float* dec_b2  = (const float*)d_in[16];  // [1]
    float* out = (float*)d_out;

    int n  = in_sizes[0] / 64;
    int ne = in_sizes[1] / 2;

    int nb256 = (n + 255) / 256;
    int eb256 = (ne + 255) / 256;

    int convBlocks = (n + 63) / 64;
    int aggBlocks  = (n + 7) / 8;  // 8 warps per block

    // CSR build via atomic allocation
    k_init<<<nb256, 256>>>(n);                          // 0
    k_deg<<<eb256, 256>>>(ei, ne);                      // 1
    k_alloc<<<nb256, 256>>>(n);                         // 2
    k_conv_gemm<<<convBlocks, 256>>>(x, conv_W, n, 0);  // 3 (profiled)
    k_scatter<<<eb256, 256>>>(ei, ne);                  // 4
    k_split_w<<<256, 256>>>(enc_W1, enc_W2);            // 5
    k_agg<<<aggBlocks, 256>>>(n, 0, conv_b, bn_g, bn_b, bn_m, bn_v);  // 6

    for (int l = 1; l < 4; l++) {
        k_conv_gemm<<<convBlocks, 256>>>(x, conv_W + l * 64 * 64, n, l);
        k_agg<<<aggBlocks, 256>>>(n, l, conv_b + l * 64, bn_g + l * 64,
                                  bn_b + l * 64, bn_m + l * 64, bn_v + l * 64);
    }

    // encoder MLP (tensor-core, bf16-split)
    dim3 e1((n + 127) / 128, 4);
    k_enc_mma<<<e1, 256>>>(enc_b1, 0, n);
    dim3 e2((n + 127) / 128, 2);
    k_enc_mma<<<e2, 256>>>(enc_b2, 1, n);

    // pooling + decoder
    k_pool<<<(n + 511) / 512, 128>>>(batch, n);
    k_final<<<GG, 64>>>(dec_W1, dec_b1, dec_W2, dec_b2, out);
}

// round 7
// speedup vs baseline: 2.4822x; 1.1334x over previous
#include <cuda_runtime.h>
#include <cuda_bf16.h>
#include <cstdint>

// ---------------- problem constants ----------------
#define NN 100000
#define NE 3200000
#define GG 64

// ---------------- mma.sync helpers ----------------
__device__ __forceinline__ uint32_t smem_u32(const void* p) {
    uint32_t a;
    asm("{ .reg .u64 t; cvta.to.shared.u64 t, %1; cvt.u32.u64 %0, t; }"
        : "=r"(a) : "l"(p));
    return a;
}

__device__ __forceinline__ void ldsm_x4(uint32_t& r0, uint32_t& r1,
                                        uint32_t& r2, uint32_t& r3,
                                        uint32_t addr) {
    asm volatile("ldmatrix.sync.aligned.m8n8.x4.shared.b16 {%0,%1,%2,%3}, [%4];"
                 : "=r"(r0), "=r"(r1), "=r"(r2), "=r"(r3) : "r"(addr));
}

__device__ __forceinline__ void mma_bf16(float* d, const uint32_t* a,
                                         const uint32_t* b) {
    asm volatile(
        "mma.sync.aligned.m16n8k16.row.col.f32.bf16.bf16.f32 "
        "{%0,%1,%2,%3}, {%4,%5,%6,%7}, {%8,%9}, {%0,%1,%2,%3};"
        : "+f"(d[0]), "+f"(d[1]), "+f"(d[2]), "+f"(d[3])
        : "r"(a[0]), "r"(a[1]), "r"(a[2]), "r"(a[3]), "r"(b[0]), "r"(b[1]));
}

// ---------------- device scratch (no allocs allowed) ----------------
__device__ float g_y[NN * 64];          // dis-scaled x@W
__device__ float g_local[NN * 256];     // concat of 4 layer outputs
__device__ float g_h1[NN * 256];        // enc layer-1 output
__device__ float g_h2[NN * 128];        // enc layer-2 output
__device__ float g_dis[NN];
__device__ int   g_cnt[NN];
__device__ int   g_rs[NN];              // CSR segment start
__device__ int   g_re[NN];              // CSR segment end
__device__ int   g_woff[NN];
__device__ int   g_src[NE];
__device__ int   g_total;
__device__ float g_gsum[GG * 128];
__device__ float g_gcnt[GG];
// pre-split, pre-transposed (n-major) weights
__device__ __nv_bfloat16 g_w1h[256 * 256];
__device__ __nv_bfloat16 g_w1l[256 * 256];
__device__ __nv_bfloat16 g_w2h[128 * 256];
__device__ __nv_bfloat16 g_w2l[128 * 256];
__device__ __nv_bfloat16 g_cwh[4 * 64 * 64];
__device__ __nv_bfloat16 g_cwl[4 * 64 * 64];

// ---------------- init: cnt=1 (self loop), zero pool + alloc counter ------
__global__ void k_init(int n) {
    int i = blockIdx.x * blockDim.x + threadIdx.x;
    if (i < n) g_cnt[i] = 1;
    if (i < GG * 128) g_gsum[i] = 0.f;
    if (i < GG) g_gcnt[i] = 0.f;
    if (i == 0) g_total = 0;
}

__global__ void k_deg(const int* __restrict__ ei, int ne) {
    int i = blockIdx.x * blockDim.x + threadIdx.x;
    if (i < ne) atomicAdd(&g_cnt[ei[ne + i]], 1);  // col = target
}

// dis + CSR segment allocation + weight split/transpose, all in one kernel.
// (grid covers n=100000 threads > 65536 split elements)
__global__ void k_alloc(int n, const float* __restrict__ W1,
                        const float* __restrict__ W2,
                        const float* __restrict__ CW) {
    int i = blockIdx.x * blockDim.x + threadIdx.x;
    if (i < n) {
        int cnt = g_cnt[i];
        g_dis[i] = rsqrtf((float)cnt);
        int indeg = cnt - 1;
        int start = atomicAdd(&g_total, indeg);
        g_rs[i] = start;
        g_re[i] = start + indeg;
        g_woff[i] = start;
    }
    // weight split+transpose (k-major -> n-major, hi/lo bf16)
    if (i < 256 * 256) {
        int nn = i >> 8, kk = i & 255;
        float v = W1[kk * 256 + nn];
        __nv_bfloat16 h = __float2bfloat16(v);
        g_w1h[i] = h;
        g_w1l[i] = __float2bfloat16(v - __bfloat162float(h));
    }
    if (i < 128 * 256) {
        int nn = i >> 8, kk = i & 255;
        float v = W2[kk * 128 + nn];
        __nv_bfloat16 h = __float2bfloat16(v);
        g_w2h[i] = h;
        g_w2l[i] = __float2bfloat16(v - __bfloat162float(h));
    }
    if (i < 4 * 64 * 64) {
        int l = i >> 12, r = i & 4095;
        int nn = r >> 6, kk = r & 63;
        float v = CW[l * 4096 + kk * 64 + nn];
        __nv_bfloat16 h = __float2bfloat16(v);
        g_cwh[i] = h;
        g_cwl[i] = __float2bfloat16(v - __bfloat162float(h));
    }
}

__global__ void k_scatter(const int* __restrict__ ei, int ne) {
    int i = blockIdx.x * blockDim.x + threadIdx.x;
    if (i < ne) {
        int c = ei[ne + i];
        int pos = atomicAdd(&g_woff[c], 1);
        g_src[pos] = ei[i];  // row = source
    }
}

// ---------------- conv GEMM via mma.sync: y = (Xin @ W_l) * dis[row] ------
// BM=128, BN=64, K=64 one-shot; 256 threads, 8 warps (4 M x 2 N), 32x32/warp
#define CPITCH 72  // bf16 per smem row (64 + 8 pad) => 144B, conflict-free ldmatrix
__global__ __launch_bounds__(256) void k_conv_mma(
    const float* __restrict__ X0, int n, int layer) {
    __shared__ __nv_bfloat16 Ah[128 * CPITCH];
    __shared__ __nv_bfloat16 Al[128 * CPITCH];
    __shared__ __nv_bfloat16 Bh[64 * CPITCH];
    __shared__ __nv_bfloat16 Bl[64 * CPITCH];

    const float* A = (layer == 0) ? X0 : (g_local + (layer - 1) * 64);
    const int lda = (layer == 0) ? 64 : 256;
    const __nv_bfloat16* Wh = g_cwh + layer * 4096;
    const __nv_bfloat16* Wl = g_cwl + layer * 4096;

    int rowBase = blockIdx.x * 128;
    int tid = threadIdx.x;
    int warp = tid >> 5, lane = tid & 31;
    int m0 = (warp >> 1) * 32;
    int n0 = (warp & 1) * 32;

    // load+split A: 128 rows x 64 cols fp32 (2048 float4 / 256 thr = 8 each)
#pragma unroll
    for (int c = 0; c < 8; c++) {
        int idx = tid + c * 256;           // 0..2047
        int r = idx >> 4, f4 = idx & 15;
        int gr = rowBase + r;
        float4 v = make_float4(0.f, 0.f, 0.f, 0.f);
        if (gr < n) v = *(const float4*)&A[gr * lda + f4 * 4];
        __nv_bfloat16 hx = __float2bfloat16(v.x);
        __nv_bfloat16 hy = __float2bfloat16(v.y);
        __nv_bfloat16 hz = __float2bfloat16(v.z);
        __nv_bfloat16 hw = __float2bfloat16(v.w);
        __nv_bfloat162 h01 = {hx, hy}, h23 = {hz, hw};
        __nv_bfloat162 l01 = {__float2bfloat16(v.x - __bfloat162float(hx)),
                              __float2bfloat16(v.y - __bfloat162float(hy))};
        __nv_bfloat162 l23 = {__float2bfloat16(v.z - __bfloat162float(hz)),
                              __float2bfloat16(v.w - __bfloat162float(hw))};
        int off = r * CPITCH + f4 * 4;
        *(__nv_bfloat162*)&Ah[off] = h01;
        *(__nv_bfloat162*)&Ah[off + 2] = h23;
        *(__nv_bfloat162*)&Al[off] = l01;
        *(__nv_bfloat162*)&Al[off + 2] = l23;
    }
    // load W (pre-split, n-major): 64 rows x 64 cols bf16 (512 uint4)
    {
#pragma unroll
        for (int c = 0; c < 2; c++) {
            int q = tid + c * 256;         // 0..511
            int r = q >> 3, ch = q & 7;    // 64 rows x 8 chunks of 8 bf16
            uint4 vh = *(const uint4*)&Wh[r * 64 + ch * 8];
            uint4 vl = *(const uint4*)&Wl[r * 64 + ch * 8];
            int off = r * CPITCH + ch * 8;
            *(uint4*)&Bh[off] = vh;
            *(uint4*)&Bl[off] = vl;
        }
    }
    __syncthreads();

    uint32_t ah_base = smem_u32(Ah);
    uint32_t al_base = smem_u32(Al);
    uint32_t bh_base = smem_u32(Bh);
    uint32_t bl_base = smem_u32(Bl);

    float acc[2][4][4];
#pragma unroll
    for (int mt = 0; mt < 2; mt++)
#pragma unroll
        for (int nt = 0; nt < 4; nt++)
#pragma unroll
            for (int q = 0; q < 4; q++) acc[mt][nt][q] = 0.f;

#pragma unroll
    for (int ks = 0; ks < 4; ks++) {
        int k0 = ks * 16;
        uint32_t aH[2][4], aL[2][4];
#pragma unroll
        for (int mt = 0; mt < 2; mt++) {
            int row = m0 + mt * 16 + (lane & 15);
            int kc = k0 + (lane >> 4) * 8;
            uint32_t byteoff = (uint32_t)(row * CPITCH + kc) * 2;
            ldsm_x4(aH[mt][0], aH[mt][1], aH[mt][2], aH[mt][3], ah_base + byteoff);
            ldsm_x4(aL[mt][0], aL[mt][1], aL[mt][2], aL[mt][3], al_base + byteoff);
        }
        uint32_t bH[4][2], bL[4][2];
#pragma unroll
        for (int ng = 0; ng < 2; ng++) {
            int rrow = n0 + ng * 16 + (lane & 7) + ((lane >> 4) & 1) * 8;
            int kc = k0 + ((lane >> 3) & 1) * 8;
            uint32_t byteoff = (uint32_t)(rrow * CPITCH + kc) * 2;
            uint32_t r0, r1, r2, r3;
            ldsm_x4(r0, r1, r2, r3, bh_base + byteoff);
            bH[ng * 2][0] = r0; bH[ng * 2][1] = r1;
            bH[ng * 2 + 1][0] = r2; bH[ng * 2 + 1][1] = r3;
            ldsm_x4(r0, r1, r2, r3, bl_base + byteoff);
            bL[ng * 2][0] = r0; bL[ng * 2][1] = r1;
            bL[ng * 2 + 1][0] = r2; bL[ng * 2 + 1][1] = r3;
        }
#pragma unroll
        for (int mt = 0; mt < 2; mt++)
#pragma unroll
            for (int nt = 0; nt < 4; nt++) {
                mma_bf16(acc[mt][nt], aH[mt], bH[nt]);
                mma_bf16(acc[mt][nt], aH[mt], bL[nt]);
                mma_bf16(acc[mt][nt], aL[mt], bH[nt]);
            }
    }

    // epilogue: scale rows by dis, store to g_y
#pragma unroll
    for (int mt = 0; mt < 2; mt++) {
        int gm0 = rowBase + m0 + mt * 16 + (lane >> 2);
        int gm1 = gm0 + 8;
        float d0 = (gm0 < n) ? g_dis[gm0] : 0.f;
        float d1 = (gm1 < n) ? g_dis[gm1] : 0.f;
#pragma unroll
        for (int nt = 0; nt < 4; nt++) {
            int gn = n0 + nt * 8 + 2 * (lane & 3);
            if (gm0 < n) {
                float2 v = {acc[mt][nt][0] * d0, acc[mt][nt][1] * d0};
                *(float2*)&g_y[gm0 * 64 + gn] = v;
            }
            if (gm1 < n) {
                float2 v = {acc[mt][nt][2] * d1, acc[mt][nt][3] * d1};
                *(float2*)&g_y[gm1 * 64 + gn] = v;
            }
        }
    }
}

// ---------------- aggregation + BN + relu + skip ----------
__global__ __launch_bounds__(256) void k_agg(
    int n, int layer,
    const float* __restrict__ bias, const float* __restrict__ gamma,
    const float* __restrict__ beta, const float* __restrict__ mean,
    const float* __restrict__ var) {
    int warp = (blockIdx.x * blockDim.x + threadIdx.x) >> 5;
    int lane = threadIdx.x & 31;
    if (warp >= n) return;
    int c = warp;
    int half = lane >> 4;
    int l16 = lane & 15;
    const float4* y4 = (const float4*)g_y;

    float4 acc;
    if (half == 0) {
        acc = y4[c * 16 + l16];  // self loop counted once
    } else {
        acc.x = 0.f; acc.y = 0.f; acc.z = 0.f; acc.w = 0.f;
    }
    int s = g_rs[c], e = g_re[c];
    for (int i = s + half; i < e; i += 2) {
        int r = g_src[i];
        float4 v = y4[r * 16 + l16];
        acc.x += v.x; acc.y += v.y; acc.z += v.z; acc.w += v.w;
    }
    acc.x += __shfl_xor_sync(0xffffffffu, acc.x, 16);
    acc.y += __shfl_xor_sync(0xffffffffu, acc.y, 16);
    acc.z += __shfl_xor_sync(0xffffffffu, acc.z, 16);
    acc.w += __shfl_xor_sync(0xffffffffu, acc.w, 16);

    if (half == 0) {
        float dc = g_dis[c];
        int d0 = l16 * 4;
        float4 ga = *(const float4*)&gamma[d0];
        float4 va = *(const float4*)&var[d0];
        float4 bi = *(const float4*)&bias[d0];
        float4 me = *(const float4*)&mean[d0];
        float4 be = *(const float4*)&beta[d0];
        float4 v;
        v.x = fmaxf((acc.x * dc + bi.x - me.x) * (ga.x * rsqrtf(va.x + 1e-5f)) + be.x, 0.f);
        v.y = fmaxf((acc.y * dc + bi.y - me.y) * (ga.y * rsqrtf(va.y + 1e-5f)) + be.y, 0.f);
        v.z = fmaxf((acc.z * dc + bi.z - me.z) * (ga.z * rsqrtf(va.z + 1e-5f)) + be.z, 0.f);
        v.w = fmaxf((acc.w * dc + bi.w - me.w) * (ga.w * rsqrtf(va.w + 1e-5f)) + be.w, 0.f);
        if (layer == 2) {
            float4 pv = *(const float4*)&g_local[c * 256 + d0];
            v.x += pv.x; v.y += pv.y; v.z += pv.z; v.w += pv.w;
        }
        *(float4*)&g_local[c * 256 + layer * 64 + d0] = v;
    }
}

// ---------------- encoder GEMM via mma.sync (bf16 split x3) ----------------
#define EPITCH 40
__global__ __launch_bounds__(256) void k_enc_mma(
    const float* __restrict__ bias, int mode, int n) {
    __shared__ __nv_bfloat16 Ah[128 * EPITCH];
    __shared__ __nv_bfloat16 Al[128 * EPITCH];
    __shared__ __nv_bfloat16 Bh[64 * EPITCH];
    __shared__ __nv_bfloat16 Bl[64 * EPITCH];

    const float* A = (mode == 0) ? g_local : g_h1;
    float* O = (mode == 0) ? g_h1 : g_h2;
    const __nv_bfloat16* Wh = (mode == 0) ? g_w1h : g_w2h;
    const __nv_bfloat16* Wl = (mode == 0) ? g_w1l : g_w2l;
    const int lda = 256;
    const int ldo = (mode == 0) ? 256 : 128;
    const int K = 256;

    int rowBase = blockIdx.x * 128;
    int colBase = blockIdx.y * 64;
    int tid = threadIdx.x;
    int warp = tid >> 5, lane = tid & 31;
    int m0 = (warp >> 1) * 32;
    int n0 = (warp & 1) * 32;

    float acc[2][4][4];
#pragma unroll
    for (int mt = 0; mt < 2; mt++)
#pragma unroll
        for (int nt = 0; nt < 4; nt++)
#pragma unroll
            for (int q = 0; q < 4; q++) acc[mt][nt][q] = 0.f;

    uint32_t ah_base = smem_u32(Ah);
    uint32_t al_base = smem_u32(Al);
    uint32_t bh_base = smem_u32(Bh);
    uint32_t bl_base = smem_u32(Bl);

    for (int kb = 0; kb < K; kb += 32) {
#pragma unroll
        for (int c = 0; c < 4; c++) {
            int idx = tid + c * 256;
            int r = idx >> 3, f4 = idx & 7;
            int gr = rowBase + r;
            float4 v = make_float4(0.f, 0.f, 0.f, 0.f);
            if (gr < n) v = *(const float4*)&A[gr * lda + kb + f4 * 4];
            __nv_bfloat16 hx = __float2bfloat16(v.x);
            __nv_bfloat16 hy = __float2bfloat16(v.y);
            __nv_bfloat16 hz = __float2bfloat16(v.z);
            __nv_bfloat16 hw = __float2bfloat16(v.w);
            __nv_bfloat162 h01 = {hx, hy}, h23 = {hz, hw};
            __nv_bfloat162 l01 = {__float2bfloat16(v.x - __bfloat162float(hx)),
                                  __float2bfloat16(v.y - __bfloat162float(hy))};
            __nv_bfloat162 l23 = {__float2bfloat16(v.z - __bfloat162float(hz)),
                                  __float2bfloat16(v.w - __bfloat162float(hw))};
            int off = r * EPITCH + f4 * 4;
            *(__nv_bfloat162*)&Ah[off] = h01;
            *(__nv_bfloat162*)&Ah[off + 2] = h23;
            *(__nv_bfloat162*)&Al[off] = l01;
            *(__nv_bfloat162*)&Al[off + 2] = l23;
        }
        {
            int r = tid >> 2, q = tid & 3;
            uint4 vh = *(const uint4*)&Wh[(colBase + r) * K + kb + q * 8];
            uint4 vl = *(const uint4*)&Wl[(colBase + r) * K + kb + q * 8];
            int off = r * EPITCH + q * 8;
            *(uint4*)&Bh[off] = vh;
            *(uint4*)&Bl[off] = vl;
        }
        __syncthreads();

#pragma unroll
        for (int ks = 0; ks < 2; ks++) {
            int k0 = ks * 16;
            uint32_t aH[2][4], aL[2][4];
#pragma unroll
            for (int mt = 0; mt < 2; mt++) {
                int row = m0 + mt * 16 + (lane & 15);
                int kc = k0 + (lane >> 4) * 8;
                uint32_t byteoff = (uint32_t)(row * EPITCH + kc) * 2;
                ldsm_x4(aH[mt][0], aH[mt][1], aH[mt][2], aH[mt][3], ah_base + byteoff);
                ldsm_x4(aL[mt][0], aL[mt][1], aL[mt][2], aL[mt][3], al_base + byteoff);
            }
            uint32_t bH[4][2], bL[4][2];
#pragma unroll
            for (int ng = 0; ng < 2; ng++) {
                int rrow = n0 + ng * 16 + (lane & 7) + ((lane >> 4) & 1) * 8;
                int kc = k0 + ((lane >> 3) & 1) * 8;
                uint32_t byteoff = (uint32_t)(rrow * EPITCH + kc) * 2;
                uint32_t r0, r1, r2, r3;
                ldsm_x4(r0, r1, r2, r3, bh_base + byteoff);
                bH[ng * 2][0] = r0; bH[ng * 2][1] = r1;
                bH[ng * 2 + 1][0] = r2; bH[ng * 2 + 1][1] = r3;
                ldsm_x4(r0, r1, r2, r3, bl_base + byteoff);
                bL[ng * 2][0] = r0; bL[ng * 2][1] = r1;
                bL[ng * 2 + 1][0] = r2; bL[ng * 2 + 1][1] = r3;
            }
#pragma unroll
            for (int mt = 0; mt < 2; mt++)
#pragma unroll
                for (int nt = 0; nt < 4; nt++) {
                    mma_bf16(acc[mt][nt], aH[mt], bH[nt]);
                    mma_bf16(acc[mt][nt], aH[mt], bL[nt]);
                    mma_bf16(acc[mt][nt], aL[mt], bH[nt]);
                }
        }
        __syncthreads();
    }

#pragma unroll
    for (int mt = 0; mt < 2; mt++)
#pragma unroll
        for (int nt = 0; nt < 4; nt++) {
            int gn = colBase + n0 + nt * 8 + 2 * (lane & 3);
            float2 bb = *(const float2*)&bias[gn];
            int gm0 = rowBase + m0 + mt * 16 + (lane >> 2);
            if (gm0 < n) {
                float2 v = {fmaxf(acc[mt][nt][0] + bb.x, 0.f),
                            fmaxf(acc[mt][nt][1] + bb.y, 0.f)};
                *(float2*)&O[gm0 * ldo + gn] = v;
            }
            int gm1 = gm0 + 8;
            if (gm1 < n) {
                float2 v = {fmaxf(acc[mt][nt][2] + bb.x, 0.f),
                            fmaxf(acc[mt][nt][3] + bb.y, 0.f)};
                *(float2*)&O[gm1 * ldo + gn] = v;
            }
        }
}

// ---------------- pooling ----------------
__global__ __launch_bounds__(128) void k_pool(const int* __restrict__ batch, int n) {
    const int NPB = 512;
    int n0 = blockIdx.x * NPB;
    if (n0 >= n) return;
    int n1 = min(n0 + NPB, n);
    int d = threadIdx.x;
    int cur = batch[n0];
    float acc = 0.f, cacc = 0.f;
    for (int nn = n0; nn < n1; nn++) {
        int g = batch[nn];
        if (g != cur) {
            atomicAdd(&g_gsum[cur * 128 + d], acc);
            if (d == 0) atomicAdd(&g_gcnt[cur], cacc);
            acc = 0.f; cacc = 0.f; cur = g;
        }
        acc += g_h2[nn * 128 + d];
        cacc += 1.f;
    }
    atomicAdd(&g_gsum[cur * 128 + d], acc);
    if (d == 0) atomicAdd(&g_gcnt[cur], cacc);
}

// ---------------- decoder ----------
__global__ __launch_bounds__(64) void k_final(
    const float* __restrict__ W1, const float* __restrict__ b1,
    const float* __restrict__ W2, const float* __restrict__ b2,
    float* __restrict__ out) {
    int g = blockIdx.x;
    int c = threadIdx.x;
    __shared__ float sh[64];
    float inv = 1.f / fmaxf(g_gcnt[g], 1.f);
    float acc = 0.f;
#pragma unroll 4
    for (int k = 0; k < 128; k++) {
        float gf = g_gsum[g * 128 + k] * inv;
        acc += gf * W1[k * 64 + c];
    }
    acc = fmaxf(acc + b1[c], 0.f);
    sh[c] = acc * W2[c];
    __syncthreads();
    if (c < 32) {
        float v = sh[c] + sh[c + 32];
        for (int off = 16; off > 0; off >>= 1)
            v += __shfl_down_sync(0xffffffffu, v, off);
        if (c == 0) out[g] = v + b2[0];
    }
}

// ---------------- launch ----------------
extern "C" void kernel_launch(void* const* d_in, const int* in_sizes, int n_in,
                              void* d_out, int out_size) {
    const float* x       = (const float*)d_in[0];
    const int*   ei      = (const int*)d_in[1];
    const int*   batch   = (const int*)d_in[2];
    const float* conv_W  = (const float*)d_in[3];
    const float* conv_b  = (const float*)d_in[4];
    const float* bn_g    = (const float*)d_in[5];
    const float* bn_b    = (const float*)d_in[6];
    const float* bn_m    = (const float*)d_in[7];
    const float* bn_v    = (const float*)d_in[8];
    const float* enc_W1  = (const float*)d_in[9];
    const float* enc_b1  = (const float*)d_in[10];
    const float* enc_W2  = (const float*)d_in[11];
    const float* enc_b2  = (const float*)d_in[12];
    const float* dec_W1  = (const float*)d_in[13];
    const float* dec_b1  = (const float*)d_in[14];
    const float* dec_W2  = (const float*)d_in[15];
    const float* dec_b2  = (const float*)d_in[16];
    float* out = (float*)d_out;

    int n  = in_sizes[0] / 64;
    int ne = in_sizes[1] / 2;

    int nb256 = (n + 255) / 256;
    int eb256 = (ne + 255) / 256;

    int convBlocks = (n + 127) / 128;
    int aggBlocks  = (n + 7) / 8;

    // CSR build + weight split (all producers before consumers)
    k_init<<<nb256, 256>>>(n);                                   // 0
    k_deg<<<eb256, 256>>>(ei, ne);                               // 1
    k_alloc<<<nb256, 256>>>(n, enc_W1, enc_W2, conv_W);          // 2 (dis+split)
    k_conv_mma<<<convBlocks, 256>>>(x, n, 0);                    // 3 (profiled)
    k_scatter<<<eb256, 256>>>(ei, ne);                           // 4
    k_agg<<<aggBlocks, 256>>>(n, 0, conv_b, bn_g, bn_b, bn_m, bn_v);  // 5

    for (int l = 1; l < 4; l++) {
        k_conv_mma<<<convBlocks, 256>>>(x, n, l);
        k_agg<<<aggBlocks, 256>>>(n, l, conv_b + l * 64, bn_g + l * 64,
                                  bn_b + l * 64, bn_m + l * 64, bn_v + l * 64);
    }

    // encoder MLP (tensor-core, bf16-split)
    dim3 e1((n + 127) / 128, 4);
    k_enc_mma<<<e1, 256>>>(enc_b1, 0, n);
    dim3 e2((n + 127) / 128, 2);
    k_enc_mma<<<e2, 256>>>(enc_b2, 1, n);

    // pooling + decoder
    k_pool<<<(n + 511) / 512, 128>>>(batch, n);
    k_final<<<GG, 64>>>(dec_W1, dec_b1, dec_W2, dec_b2, out);
}